// round 4
// baseline (speedup 1.0000x reference)
#include <cuda_runtime.h>
#include <cstdint>

// Problem constants
#define NN 50000
#define EE 1600000
#define DD 64
#define D2 32          // float2 columns per row
#define K0 319999u     // floor(0.2*(E-1))
#define K1 320000u
#define QFRAC 0.8f
#define EPS 1e-16f

// ---------------- device scratch (static, no allocation) ----------------
__device__ unsigned g_hist[2][256];
__device__ unsigned g_pref[2];
__device__ unsigned g_rank[2];
__device__ float    g_thr;

__device__ float    g_attsums[NN];
__device__ unsigned g_deg[NN];
__device__ unsigned g_rowstart[NN + 1];
__device__ unsigned g_cursor[NN];

__device__ int      g_srcs[EE];
__device__ float    g_w[EE];

__device__ float    g_Y1[NN * DD];
__device__ float    g_Y2[NN * DD];
__device__ float    g_S [NN * DD];

// ---------------- init / zero ----------------
__global__ void k_zero() {
    int i = blockIdx.x * blockDim.x + threadIdx.x;
    if (i < NN) { g_attsums[i] = 0.f; g_deg[i] = 0u; }
    if (i < 512) ((unsigned*)g_hist)[i] = 0u;
    if (i == 0) {
        g_pref[0] = 0u; g_pref[1] = 0u;
        g_rank[0] = K0; g_rank[1] = K1;
    }
}

// ---------------- radix select (4 passes of 8 bits, MSB first) ----------------
// att values are uniform [0,1): positive floats, so the uint bit pattern is
// order-isomorphic to the float value.
__global__ void k_hist(const float* __restrict__ att, int p) {
    __shared__ unsigned sh[512];
    for (int i = threadIdx.x; i < 512; i += blockDim.x) sh[i] = 0u;
    __syncthreads();
    unsigned pref0 = g_pref[0], pref1 = g_pref[1];
    int shamt = 24 - 8 * p;
    int stride = gridDim.x * blockDim.x;
    for (int e = blockIdx.x * blockDim.x + threadIdx.x; e < EE; e += stride) {
        unsigned key = __float_as_uint(att[e]);
        unsigned b = (key >> shamt) & 255u;
        if (p == 0) {
            atomicAdd(&sh[b], 1u);
            atomicAdd(&sh[256 + b], 1u);
        } else {
            unsigned hi = key >> (32 - 8 * p);
            if (hi == pref0) atomicAdd(&sh[b], 1u);
            if (hi == pref1) atomicAdd(&sh[256 + b], 1u);
        }
    }
    __syncthreads();
    for (int i = threadIdx.x; i < 512; i += blockDim.x) {
        unsigned v = sh[i];
        if (v) atomicAdd(&((unsigned*)g_hist)[i], v);
    }
}

__global__ void k_resolve(int p) {
    __shared__ unsigned s[256];
    int t = threadIdx.x;
    for (int sel = 0; sel < 2; sel++) {
        unsigned c = g_hist[sel][t];
        s[t] = c;
        __syncthreads();
        // inclusive scan (Hillis-Steele)
        for (int off = 1; off < 256; off <<= 1) {
            unsigned v = (t >= off) ? s[t - off] : 0u;
            __syncthreads();
            s[t] += v;
            __syncthreads();
        }
        unsigned cum  = s[t];
        unsigned rank = g_rank[sel];       // snapshot BEFORE any write
        unsigned pref = g_pref[sel];
        __syncthreads();                   // all reads done before the write below
        if (rank < cum && rank >= cum - c) {
            g_pref[sel] = (pref << 8) | (unsigned)t;
            g_rank[sel] = rank - (cum - c);
        }
        g_hist[sel][t] = 0u;               // ready for next pass
        __syncthreads();
    }
    if (p == 3 && t == 0) {
        float v0 = __uint_as_float(g_pref[0]);
        float v1 = __uint_as_float(g_pref[1]);
        g_thr = v0 + QFRAC * (v1 - v0);
    }
}

// ---------------- edge pass 1: att_sums over src + degree over dst ----------------
__global__ void k_edge1(const float* __restrict__ att,
                        const int* __restrict__ src,
                        const int* __restrict__ dst) {
    int e = blockIdx.x * blockDim.x + threadIdx.x;
    if (e >= EE) return;
    float thr = g_thr;
    float a = att[e];
    int s = src[e];
    int d = dst[e];
    if (a > thr) atomicAdd(&g_attsums[s], a);
    atomicAdd(&g_deg[d], 1u);
}

// ---------------- exclusive prefix over degrees (single block) ----------------
__global__ void k_scan() {
    __shared__ unsigned ps[1024];
    const int C = 49;                     // 1024*49 >= 50000
    int t = threadIdx.x;
    int base = t * C;
    unsigned sum = 0;
    #pragma unroll 7
    for (int i = 0; i < C; i++) {
        int j = base + i;
        if (j < NN) sum += g_deg[j];
    }
    ps[t] = sum;
    __syncthreads();
    for (int off = 1; off < 1024; off <<= 1) {
        unsigned v = (t >= off) ? ps[t - off] : 0u;
        __syncthreads();
        ps[t] += v;
        __syncthreads();
    }
    unsigned run = (t == 0) ? 0u : ps[t - 1];
    for (int i = 0; i < C; i++) {
        int j = base + i;
        if (j < NN) {
            g_rowstart[j] = run;
            g_cursor[j]   = run;
            run += g_deg[j];
        }
    }
    if (t == 1023) g_rowstart[NN] = ps[1023];
}

// ---------------- scatter edges into dst-sorted CSR, with weights ----------------
__global__ void k_scatter(const float* __restrict__ att,
                          const int* __restrict__ src,
                          const int* __restrict__ dst) {
    int e = blockIdx.x * blockDim.x + threadIdx.x;
    if (e >= EE) return;
    float thr = g_thr;
    float a = att[e];
    int s = src[e];
    int d = dst[e];
    float m = (a > thr) ? a : 0.f;
    float w = m / (g_attsums[s] + EPS);
    unsigned pos = atomicAdd(&g_cursor[d], 1u);
    g_srcs[pos] = s;
    g_w[pos] = w;
}

// ---------------- fused RK4 stage: az = A*Yin; k = az - Yin; S update; Yout ----------------
// MODE 1: Yin=x,  Yout=Y1, S  = k,        Yout = x + 0.5k
// MODE 2: Yin=Y1, Yout=Y2, S += 2k,       Yout = x + 0.5k
// MODE 3: Yin=Y2, Yout=Y1, S += 2k,       Yout = x + k
// MODE 4: Yin=Y1, Yout=out,               out  = x + (S + k)/6
template <int MODE>
__global__ void k_stage(const float2* __restrict__ x, float2* __restrict__ out) {
    int gw   = (blockIdx.x * blockDim.x + threadIdx.x) >> 5;
    int lane = threadIdx.x & 31;
    if (gw >= NN) return;

    const float2* Yin;
    float2* Yout;
    if (MODE == 1)      { Yin = x;                   Yout = (float2*)g_Y1; }
    else if (MODE == 2) { Yin = (const float2*)g_Y1; Yout = (float2*)g_Y2; }
    else if (MODE == 3) { Yin = (const float2*)g_Y2; Yout = (float2*)g_Y1; }
    else                { Yin = (const float2*)g_Y1; Yout = out; }

    unsigned e0 = g_rowstart[gw];
    unsigned e1 = g_rowstart[gw + 1];

    float ax = 0.f, ay = 0.f;
    for (unsigned e = e0; e < e1; e++) {
        int s = __ldg(&g_srcs[e]);
        float wt = __ldg(&g_w[e]);
        float2 y = __ldg(&Yin[s * D2 + lane]);
        ax = fmaf(wt, y.x, ax);
        ay = fmaf(wt, y.y, ay);
    }

    int idx = gw * D2 + lane;
    float2 yr = Yin[idx];
    float kx = ax - yr.x;
    float ky = ay - yr.y;
    float2 xr = x[idx];
    float2* S2 = (float2*)g_S;

    if (MODE == 1) {
        S2[idx] = make_float2(kx, ky);
        Yout[idx] = make_float2(xr.x + 0.5f * kx, xr.y + 0.5f * ky);
    } else if (MODE == 2) {
        float2 s = S2[idx];
        S2[idx] = make_float2(s.x + 2.f * kx, s.y + 2.f * ky);
        Yout[idx] = make_float2(xr.x + 0.5f * kx, xr.y + 0.5f * ky);
    } else if (MODE == 3) {
        float2 s = S2[idx];
        S2[idx] = make_float2(s.x + 2.f * kx, s.y + 2.f * ky);
        Yout[idx] = make_float2(xr.x + kx, xr.y + ky);
    } else {
        float2 s = S2[idx];
        const float c = 1.f / 6.f;
        Yout[idx] = make_float2(xr.x + (s.x + kx) * c, xr.y + (s.y + ky) * c);
    }
}

// ---------------- launch ----------------
extern "C" void kernel_launch(void* const* d_in, const int* in_sizes, int n_in,
                              void* d_out, int out_size) {
    const float* x   = (const float*)d_in[0];   // [50000, 64]
    const float* att = (const float*)d_in[1];   // [1600000, 1]
    const int*   ei  = (const int*)d_in[2];     // [2, 1600000]
    const int* src = ei;
    const int* dst = ei + EE;
    float* out = (float*)d_out;

    const int T = 256;
    const int zb = (NN + T - 1) / T;
    const int eb = (EE + T - 1) / T;
    const int sb = (NN * 32 + T - 1) / T;   // 1 warp per node row

    k_zero<<<zb, T>>>();

    for (int p = 0; p < 4; p++) {
        k_hist<<<1024, T>>>(att, p);
        k_resolve<<<1, 256>>>(p);
    }

    k_edge1<<<eb, T>>>(att, src, dst);
    k_scan<<<1, 1024>>>();
    k_scatter<<<eb, T>>>(att, src, dst);

    k_stage<1><<<sb, T>>>((const float2*)x, (float2*)out);
    k_stage<2><<<sb, T>>>((const float2*)x, (float2*)out);
    k_stage<3><<<sb, T>>>((const float2*)x, (float2*)out);
    k_stage<4><<<sb, T>>>((const float2*)x, (float2*)out);
}